// round 6
// baseline (speedup 1.0000x reference)
#include <cuda_runtime.h>
#include <cstdint>

#define DEVI __device__ __forceinline__

static constexpr int Mdim = 8192;
static constexpr int Ndim = 4096;
static constexpr int Kdim = 2048;
static constexpr int BM = 128;
static constexpr int BN = 128;
static constexpr int BK = 128;                 // s8 elements (=bytes) per stage chunk
static constexpr int NKC = Kdim / BK;          // 16
static constexpr int NT = 512;                 // 16 warps: 4 (M) x 4 (N)
static constexpr float EPS = 1e-5f;

// smem: [0,1024): sbias(128f) + ssb(128f) ; stages follow
static constexpr unsigned SM_STAGE = 1024;
static constexpr unsigned ROWP = 144;                       // padded row bytes (128B data)
static constexpr unsigned REG_BYTES = 128u * ROWP;          // 18432 per tensor region
static constexpr unsigned OFF_A1 = 0;
static constexpr unsigned OFF_A2 = 1 * REG_BYTES;
static constexpr unsigned OFF_B1 = 2 * REG_BYTES;
static constexpr unsigned OFF_B2 = 3 * REG_BYTES;
static constexpr unsigned STAGE_BYTES = 4 * REG_BYTES;      // 73728
static constexpr unsigned SMEM_TOTAL = SM_STAGE + 2 * STAGE_BYTES;  // 148480
static constexpr int EPS_LD = 132;                          // epilogue row stride (floats)

// quantized operands + per-row scales
__device__ __align__(128) int8_t g_A1[(size_t)Mdim * Kdim];
__device__ __align__(128) int8_t g_A2[(size_t)Mdim * Kdim];
__device__ __align__(128) int8_t g_B1[(size_t)Ndim * Kdim];
__device__ __align__(128) int8_t g_B2[(size_t)Ndim * Kdim];
__device__ float g_sA[Mdim];
__device__ float g_sB[Ndim];

DEVI uint32_t smem_u32(const void* p) {
    uint32_t a;
    asm("{ .reg .u64 t; cvta.to.shared.u64 t, %1; cvt.u32.u64 %0, t; }" : "=r"(a) : "l"(p));
    return a;
}
DEVI void cpa16(uint32_t dst, const void* src) {
    asm volatile("cp.async.cg.shared.global [%0], [%1], 16;\n" :: "r"(dst), "l"(src));
}
DEVI void cpa_commit() { asm volatile("cp.async.commit_group;\n" ::: "memory"); }
DEVI void cpa_wait0()  { asm volatile("cp.async.wait_group 0;\n" ::: "memory"); }
DEVI void cpa_wait1()  { asm volatile("cp.async.wait_group 1;\n" ::: "memory"); }

DEVI void ldsm4(uint32_t (&r)[4], uint32_t addr) {
    asm volatile("ldmatrix.sync.aligned.m8n8.x4.shared.b16 {%0,%1,%2,%3}, [%4];"
                 : "=r"(r[0]), "=r"(r[1]), "=r"(r[2]), "=r"(r[3]) : "r"(addr));
}
DEVI void imma(int (&c)[4], const uint32_t (&a)[4], const uint32_t* b) {
    asm volatile(
        "mma.sync.aligned.m16n8k32.row.col.s32.s8.s8.s32 "
        "{%0,%1,%2,%3}, {%4,%5,%6,%7}, {%8,%9}, {%0,%1,%2,%3};"
        : "+r"(c[0]), "+r"(c[1]), "+r"(c[2]), "+r"(c[3])
        : "r"(a[0]), "r"(a[1]), "r"(a[2]), "r"(a[3]), "r"(b[0]), "r"(b[1]));
}

// ---------------- fp32 -> int8 pair quantization (per-row scale) ----------------
DEVI int pack4(int a, int b, int c, int d) {
    return (a & 0xFF) | ((b & 0xFF) << 8) | ((c & 0xFF) << 16) | ((d & 0xFF) << 24);
}
DEVI void qsplit(float x, float inv, int& h, int& l) {
    float q = x * inv;                          // in [-16256, 16256]
    float x1 = rintf(q * 0.0078125f);           // round(q/128) in [-127,127]
    float x2 = rintf(fmaf(-128.f, x1, q));      // in [-64,64]
    h = (int)x1; l = (int)x2;
}

DEVI void quant_row(const float4* __restrict__ src, int* __restrict__ q1,
                    int* __restrict__ q2, float* __restrict__ sc) {
    __shared__ float red[8];
    const int row = blockIdx.x;
    const int tid = threadIdx.x;
    const float4* rp = src + (size_t)row * (Kdim / 4);
    float4 v0 = rp[tid];
    float4 v1 = rp[tid + 256];
    float m = fmaxf(fmaxf(fabsf(v0.x), fabsf(v0.y)), fmaxf(fabsf(v0.z), fabsf(v0.w)));
    m = fmaxf(m, fmaxf(fmaxf(fabsf(v1.x), fabsf(v1.y)), fmaxf(fabsf(v1.z), fabsf(v1.w))));
#pragma unroll
    for (int off = 16; off > 0; off >>= 1)
        m = fmaxf(m, __shfl_xor_sync(0xFFFFFFFFu, m, off));
    if ((tid & 31) == 0) red[tid >> 5] = m;
    __syncthreads();
    float rmax = red[0];
#pragma unroll
    for (int i = 1; i < 8; i++) rmax = fmaxf(rmax, red[i]);

    const float sA = rmax > 0.f ? rmax * (1.0f / 16256.0f) : 1.0f;
    if (tid == 0) sc[row] = sA;
    const float inv = 1.0f / sA;

    int h0, l0, h1, l1, h2, l2, h3, l3;
    qsplit(v0.x, inv, h0, l0); qsplit(v0.y, inv, h1, l1);
    qsplit(v0.z, inv, h2, l2); qsplit(v0.w, inv, h3, l3);
    q1[(size_t)row * (Kdim / 4) + tid] = pack4(h0, h1, h2, h3);
    q2[(size_t)row * (Kdim / 4) + tid] = pack4(l0, l1, l2, l3);
    qsplit(v1.x, inv, h0, l0); qsplit(v1.y, inv, h1, l1);
    qsplit(v1.z, inv, h2, l2); qsplit(v1.w, inv, h3, l3);
    q1[(size_t)row * (Kdim / 4) + tid + 256] = pack4(h0, h1, h2, h3);
    q2[(size_t)row * (Kdim / 4) + tid + 256] = pack4(l0, l1, l2, l3);
}

__global__ void __launch_bounds__(256) quant_A_kernel(const float4* __restrict__ s) {
    quant_row(s, reinterpret_cast<int*>(g_A1), reinterpret_cast<int*>(g_A2), g_sA);
}
__global__ void __launch_bounds__(256) quant_B_kernel(const float4* __restrict__ s) {
    quant_row(s, reinterpret_cast<int*>(g_B1), reinterpret_cast<int*>(g_B2), g_sB);
}

// ---------------- fused int8x3 GEMM + scale + bias + GroupNorm + hardtanh ----------------
__global__ void __launch_bounds__(NT, 1)
gemm_gn_kernel(const float* __restrict__ bias, float* __restrict__ out) {
    extern __shared__ __align__(16) char smem[];
    const uint32_t sb = smem_u32(smem);
    const int tid = threadIdx.x;
    const int lane = tid & 31;
    const int w = tid >> 5;           // 0..15
    const int wr = w >> 2;            // 0..3  (M)
    const int wc = w & 3;             // 0..3  (N)
    const int m0 = blockIdx.y * BM;
    const int n0 = blockIdx.x * BN;

    float* sbias = reinterpret_cast<float*>(smem);            // [0,128)
    float* ssb = reinterpret_cast<float*>(smem) + 128;        // [128,256)
    if (tid < BN) {
        sbias[tid] = bias[n0 + tid];
        ssb[tid] = g_sB[n0 + tid];
    }

    // ldmatrix offsets (bytes, relative to region base)
    uint32_t aoff[2];
#pragma unroll
    for (int mf = 0; mf < 2; mf++)
        aoff[mf] = (uint32_t)((wr * 32 + mf * 16 + (lane & 15)) * ROWP + (lane >> 4) * 16);
    uint32_t boff[2];
    {
        int brow = wc * 32 + (lane & 7) + ((lane >> 4) << 3);
        boff[0] = (uint32_t)(brow * ROWP + ((lane >> 3) & 1) * 16);
        boff[1] = (uint32_t)((brow + 16) * ROWP + ((lane >> 3) & 1) * 16);
    }

    const char* pA1 = reinterpret_cast<const char*>(g_A1) + (size_t)m0 * Kdim;
    const char* pA2 = reinterpret_cast<const char*>(g_A2) + (size_t)m0 * Kdim;
    const char* pB1 = reinterpret_cast<const char*>(g_B1) + (size_t)n0 * Kdim;
    const char* pB2 = reinterpret_cast<const char*>(g_B2) + (size_t)n0 * Kdim;

    auto load_stage = [&](int buf, int kc) {
        const uint32_t st = sb + SM_STAGE + (uint32_t)buf * STAGE_BYTES;
        const int k0 = kc * BK;                       // byte offset along K
        const char* bases[4] = {pA1, pA2, pB1, pB2};
#pragma unroll
        for (int r4 = 0; r4 < 4; r4++) {
            const uint32_t dst0 = st + (uint32_t)r4 * REG_BYTES;
#pragma unroll
            for (int q = 0; q < 2; q++) {
                int idx = tid + q * NT;               // 0..1023
                int row = idx >> 3;
                int cc = (idx & 7) * 16;
                cpa16(dst0 + (uint32_t)(row * (int)ROWP + cc),
                      bases[r4] + (size_t)row * Kdim + (size_t)(k0 + cc));
            }
        }
    };

    int acch[2][4][4];   // x1*y1
    int accm[2][4][4];   // x1*y2 + x2*y1
#pragma unroll
    for (int mf = 0; mf < 2; mf++)
#pragma unroll
        for (int nf = 0; nf < 4; nf++)
#pragma unroll
            for (int i = 0; i < 4; i++) { acch[mf][nf][i] = 0; accm[mf][nf][i] = 0; }

    load_stage(0, 0); cpa_commit();
    load_stage(1, 1); cpa_commit();

    for (int kc = 0; kc < NKC; kc++) {
        if (kc == NKC - 1) cpa_wait0(); else cpa_wait1();
        __syncthreads();

        const uint32_t st = sb + SM_STAGE + (uint32_t)(kc & 1) * STAGE_BYTES;
        const uint32_t sA1 = st + OFF_A1, sA2 = st + OFF_A2;
        const uint32_t sB1 = st + OFF_B1, sB2 = st + OFF_B2;

#pragma unroll
        for (int ks = 0; ks < 4; ks++) {
            const uint32_t ko = (uint32_t)(ks * 32);   // +32 s8 per k-step
            uint32_t a1[2][4], a2[2][4];
#pragma unroll
            for (int mf = 0; mf < 2; mf++) {
                ldsm4(a1[mf], sA1 + aoff[mf] + ko);
                ldsm4(a2[mf], sA2 + aoff[mf] + ko);
            }
            uint32_t b1[4][2], b2[4][2];
#pragma unroll
            for (int np = 0; np < 2; np++) {
                uint32_t t[4];
                ldsm4(t, sB1 + boff[np] + ko);
                b1[2 * np][0] = t[0]; b1[2 * np][1] = t[1];
                b1[2 * np + 1][0] = t[2]; b1[2 * np + 1][1] = t[3];
                ldsm4(t, sB2 + boff[np] + ko);
                b2[2 * np][0] = t[0]; b2[2 * np][1] = t[1];
                b2[2 * np + 1][0] = t[2]; b2[2 * np + 1][1] = t[3];
            }
#pragma unroll
            for (int mf = 0; mf < 2; mf++)
#pragma unroll
                for (int nf = 0; nf < 4; nf++) {
                    imma(acch[mf][nf], a1[mf], b1[nf]);
                    imma(accm[mf][nf], a1[mf], b2[nf]);
                    imma(accm[mf][nf], a2[mf], b1[nf]);
                }
        }
        __syncthreads();
        if (kc + 2 < NKC) { load_stage(kc & 1, kc + 2); cpa_commit(); }
    }

    // -------- epilogue: raw = 16384*hi + 128*mid staged in smem; GroupNorm per row --------
    float* ep = reinterpret_cast<float*>(smem + SM_STAGE);
    {
        const int r0 = wr * 32 + (lane >> 2);
        const int c0 = wc * 32 + (lane & 3) * 2;
#pragma unroll
        for (int mf = 0; mf < 2; mf++)
#pragma unroll
            for (int nf = 0; nf < 4; nf++) {
                const int r = r0 + mf * 16;
                const int c = c0 + nf * 8;
                float2 v0, v1;
                v0.x = fmaf(16384.f, (float)acch[mf][nf][0], 128.f * (float)accm[mf][nf][0]);
                v0.y = fmaf(16384.f, (float)acch[mf][nf][1], 128.f * (float)accm[mf][nf][1]);
                v1.x = fmaf(16384.f, (float)acch[mf][nf][2], 128.f * (float)accm[mf][nf][2]);
                v1.y = fmaf(16384.f, (float)acch[mf][nf][3], 128.f * (float)accm[mf][nf][3]);
                *reinterpret_cast<float2*>(ep + (size_t)r * EPS_LD + c) = v0;
                *reinterpret_cast<float2*>(ep + (size_t)(r + 8) * EPS_LD + c) = v1;
            }
    }
    __syncthreads();

    if (tid < BM) {
        const float sAr = g_sA[m0 + tid];
        const float4* row = reinterpret_cast<const float4*>(ep + (size_t)tid * EPS_LD);
        const float4* sb4 = reinterpret_cast<const float4*>(sbias);
        const float4* sc4 = reinterpret_cast<const float4*>(ssb);
        float sum = 0.f, sq = 0.f;
#pragma unroll
        for (int i = 0; i < 32; i++) {
            float4 v = row[i];
            float4 s = sc4[i];
            float4 b = sb4[i];
            float f0 = fmaf(sAr * s.x, v.x, b.x);
            float f1 = fmaf(sAr * s.y, v.y, b.y);
            float f2 = fmaf(sAr * s.z, v.z, b.z);
            float f3 = fmaf(sAr * s.w, v.w, b.w);
            sum += f0 + f1 + f2 + f3;
            sq += f0 * f0 + f1 * f1 + f2 * f2 + f3 * f3;
        }
        const float mean = sum * (1.0f / 128.0f);
        const float rstd = rsqrtf(sq * (1.0f / 128.0f) - mean * mean + EPS);
        float4* po = reinterpret_cast<float4*>(out + (size_t)(m0 + tid) * Ndim + n0);
#pragma unroll
        for (int i = 0; i < 32; i++) {
            float4 v = row[i];
            float4 s = sc4[i];
            float4 b = sb4[i];
            float4 o;
            o.x = fminf(fmaxf((fmaf(sAr * s.x, v.x, b.x) - mean) * rstd, -1.f), 1.f);
            o.y = fminf(fmaxf((fmaf(sAr * s.y, v.y, b.y) - mean) * rstd, -1.f), 1.f);
            o.z = fminf(fmaxf((fmaf(sAr * s.z, v.z, b.z) - mean) * rstd, -1.f), 1.f);
            o.w = fminf(fmaxf((fmaf(sAr * s.w, v.w, b.w) - mean) * rstd, -1.f), 1.f);
            po[i] = o;
        }
    }
}

extern "C" void kernel_launch(void* const* d_in, const int* in_sizes, int n_in,
                              void* d_out, int out_size) {
    const float* x = (const float*)d_in[0];
    const float* wgt = (const float*)d_in[1];
    const float* bias = (const float*)d_in[2];
    float* out = (float*)d_out;

    cudaFuncSetAttribute(gemm_gn_kernel, cudaFuncAttributeMaxDynamicSharedMemorySize,
                         (int)SMEM_TOTAL);

    quant_A_kernel<<<Mdim, 256>>>((const float4*)x);
    quant_B_kernel<<<Ndim, 256>>>((const float4*)wgt);

    dim3 grid(Ndim / BN, Mdim / BM);   // (32, 64), x-fastest -> B set L2-resident
    gemm_gn_kernel<<<grid, NT, SMEM_TOTAL>>>(bias, out);
}

// round 7
// speedup vs baseline: 1.0308x; 1.0308x over previous
#include <cuda_runtime.h>
#include <cstdint>

#define DEVI __device__ __forceinline__

static constexpr int Mdim = 8192;
static constexpr int Ndim = 4096;
static constexpr int Kdim = 2048;
static constexpr int BM = 128;
static constexpr int BN = 128;
static constexpr int BK = 128;                 // s8 elements (=bytes) per stage chunk
static constexpr int NKC = Kdim / BK;          // 16
static constexpr int NT = 256;                 // 8 warps: 2 (M) x 4 (N)
static constexpr float EPS = 1e-5f;

// smem: [0,1024): sbias(128f) + ssb(128f) ; 3 stages follow
static constexpr unsigned SM_STAGE = 1024;
static constexpr unsigned ROWP = 144;                       // padded row bytes (128B data)
static constexpr unsigned REG_BYTES = 128u * ROWP;          // 18432 per tensor region
static constexpr unsigned OFF_A1 = 0;
static constexpr unsigned OFF_A2 = 1 * REG_BYTES;
static constexpr unsigned OFF_B1 = 2 * REG_BYTES;
static constexpr unsigned OFF_B2 = 3 * REG_BYTES;
static constexpr unsigned STAGE_BYTES = 4 * REG_BYTES;      // 73728
static constexpr unsigned SMEM_TOTAL = SM_STAGE + 3 * STAGE_BYTES;  // 222208
static constexpr int EPS_LD = 132;                          // epilogue row stride (floats)

// quantized operands + per-row scales
__device__ __align__(128) int8_t g_A1[(size_t)Mdim * Kdim];
__device__ __align__(128) int8_t g_A2[(size_t)Mdim * Kdim];
__device__ __align__(128) int8_t g_B1[(size_t)Ndim * Kdim];
__device__ __align__(128) int8_t g_B2[(size_t)Ndim * Kdim];
__device__ float g_sA[Mdim];
__device__ float g_sB[Ndim];

DEVI uint32_t smem_u32(const void* p) {
    uint32_t a;
    asm("{ .reg .u64 t; cvta.to.shared.u64 t, %1; cvt.u32.u64 %0, t; }" : "=r"(a) : "l"(p));
    return a;
}
DEVI void cpa16(uint32_t dst, const void* src) {
    asm volatile("cp.async.cg.shared.global [%0], [%1], 16;\n" :: "r"(dst), "l"(src));
}
DEVI void cpa_commit() { asm volatile("cp.async.commit_group;\n" ::: "memory"); }
DEVI void cpa_wait0()  { asm volatile("cp.async.wait_group 0;\n" ::: "memory"); }
DEVI void cpa_wait1()  { asm volatile("cp.async.wait_group 1;\n" ::: "memory"); }

DEVI void ldsm4(uint32_t (&r)[4], uint32_t addr) {
    asm volatile("ldmatrix.sync.aligned.m8n8.x4.shared.b16 {%0,%1,%2,%3}, [%4];"
                 : "=r"(r[0]), "=r"(r[1]), "=r"(r[2]), "=r"(r[3]) : "r"(addr));
}
DEVI void imma(int (&c)[4], const uint32_t (&a)[4], const uint32_t* b) {
    asm volatile(
        "mma.sync.aligned.m16n8k32.row.col.s32.s8.s8.s32 "
        "{%0,%1,%2,%3}, {%4,%5,%6,%7}, {%8,%9}, {%0,%1,%2,%3};"
        : "+r"(c[0]), "+r"(c[1]), "+r"(c[2]), "+r"(c[3])
        : "r"(a[0]), "r"(a[1]), "r"(a[2]), "r"(a[3]), "r"(b[0]), "r"(b[1]));
}

// ---------------- fp32 -> int8 pair quantization (per-row scale) ----------------
DEVI int pack4(int a, int b, int c, int d) {
    return (a & 0xFF) | ((b & 0xFF) << 8) | ((c & 0xFF) << 16) | ((d & 0xFF) << 24);
}
DEVI void qsplit(float x, float inv, int& h, int& l) {
    float q = x * inv;                          // in [-16256, 16256]
    float x1 = rintf(q * 0.0078125f);           // round(q/128) in [-127,127]
    float x2 = rintf(fmaf(-128.f, x1, q));      // in [-64,64]
    h = (int)x1; l = (int)x2;
}

DEVI void quant_row(const float4* __restrict__ src, int row, int* __restrict__ q1,
                    int* __restrict__ q2, float* __restrict__ sc) {
    __shared__ float red[8];
    const int tid = threadIdx.x;
    const float4* rp = src + (size_t)row * (Kdim / 4);
    float4 v0 = rp[tid];
    float4 v1 = rp[tid + 256];
    float m = fmaxf(fmaxf(fabsf(v0.x), fabsf(v0.y)), fmaxf(fabsf(v0.z), fabsf(v0.w)));
    m = fmaxf(m, fmaxf(fmaxf(fabsf(v1.x), fabsf(v1.y)), fmaxf(fabsf(v1.z), fabsf(v1.w))));
#pragma unroll
    for (int off = 16; off > 0; off >>= 1)
        m = fmaxf(m, __shfl_xor_sync(0xFFFFFFFFu, m, off));
    if ((tid & 31) == 0) red[tid >> 5] = m;
    __syncthreads();
    float rmax = red[0];
#pragma unroll
    for (int i = 1; i < 8; i++) rmax = fmaxf(rmax, red[i]);

    const float sA = rmax > 0.f ? rmax * (1.0f / 16256.0f) : 1.0f;
    if (tid == 0) sc[row] = sA;
    const float inv = 1.0f / sA;

    int h0, l0, h1, l1, h2, l2, h3, l3;
    qsplit(v0.x, inv, h0, l0); qsplit(v0.y, inv, h1, l1);
    qsplit(v0.z, inv, h2, l2); qsplit(v0.w, inv, h3, l3);
    q1[(size_t)row * (Kdim / 4) + tid] = pack4(h0, h1, h2, h3);
    q2[(size_t)row * (Kdim / 4) + tid] = pack4(l0, l1, l2, l3);
    qsplit(v1.x, inv, h0, l0); qsplit(v1.y, inv, h1, l1);
    qsplit(v1.z, inv, h2, l2); qsplit(v1.w, inv, h3, l3);
    q1[(size_t)row * (Kdim / 4) + tid + 256] = pack4(h0, h1, h2, h3);
    q2[(size_t)row * (Kdim / 4) + tid + 256] = pack4(l0, l1, l2, l3);
}

// merged: blocks [0,Mdim) quantize A rows, [Mdim,Mdim+Ndim) quantize B rows
__global__ void __launch_bounds__(256) quant_AB_kernel(const float4* __restrict__ x,
                                                       const float4* __restrict__ wgt) {
    const int b = blockIdx.x;
    if (b < Mdim) {
        quant_row(x, b, reinterpret_cast<int*>(g_A1), reinterpret_cast<int*>(g_A2), g_sA);
    } else {
        quant_row(wgt, b - Mdim, reinterpret_cast<int*>(g_B1), reinterpret_cast<int*>(g_B2), g_sB);
    }
}

// ---------------- fused int8x3 GEMM + scale + bias + GroupNorm + hardtanh ----------------
__global__ void __launch_bounds__(NT, 1)
gemm_gn_kernel(const float* __restrict__ bias, float* __restrict__ out) {
    extern __shared__ __align__(16) char smem[];
    const uint32_t sb = smem_u32(smem);
    const int tid = threadIdx.x;
    const int lane = tid & 31;
    const int w = tid >> 5;
    const int wr = w >> 2;            // 0..1  (M)
    const int wc = w & 3;             // 0..3  (N)
    const int m0 = blockIdx.y * BM;
    const int n0 = blockIdx.x * BN;

    float* sbias = reinterpret_cast<float*>(smem);            // [0,128)
    float* ssb = reinterpret_cast<float*>(smem) + 128;        // [128,256)
    if (tid < BN) {
        sbias[tid] = bias[n0 + tid];
        ssb[tid] = g_sB[n0 + tid];
    }

    // ldmatrix offsets (bytes, relative to region base)
    uint32_t aoff[4];
#pragma unroll
    for (int mf = 0; mf < 4; mf++)
        aoff[mf] = (uint32_t)((wr * 64 + mf * 16 + (lane & 15)) * ROWP + (lane >> 4) * 16);
    uint32_t boff[2];
    {
        int brow = wc * 32 + (lane & 7) + ((lane >> 4) << 3);
        boff[0] = (uint32_t)(brow * ROWP + ((lane >> 3) & 1) * 16);
        boff[1] = (uint32_t)((brow + 16) * ROWP + ((lane >> 3) & 1) * 16);
    }

    const char* pA1 = reinterpret_cast<const char*>(g_A1) + (size_t)m0 * Kdim;
    const char* pA2 = reinterpret_cast<const char*>(g_A2) + (size_t)m0 * Kdim;
    const char* pB1 = reinterpret_cast<const char*>(g_B1) + (size_t)n0 * Kdim;
    const char* pB2 = reinterpret_cast<const char*>(g_B2) + (size_t)n0 * Kdim;

    auto load_stage = [&](int buf, int kc) {
        const uint32_t st = sb + SM_STAGE + (uint32_t)buf * STAGE_BYTES;
        const int k0 = kc * BK;                       // byte offset along K
        const char* bases[4] = {pA1, pA2, pB1, pB2};
#pragma unroll
        for (int r4 = 0; r4 < 4; r4++) {
            const uint32_t dst0 = st + (uint32_t)r4 * REG_BYTES;
#pragma unroll
            for (int q = 0; q < 4; q++) {
                int idx = tid + q * NT;               // 0..1023
                int row = idx >> 3;
                int cc = (idx & 7) * 16;
                cpa16(dst0 + (uint32_t)(row * (int)ROWP + cc),
                      bases[r4] + (size_t)row * Kdim + (size_t)(k0 + cc));
            }
        }
    };

    int acch[4][4][4];   // x1*y1
    int accm[4][4][4];   // x1*y2 + x2*y1
#pragma unroll
    for (int mf = 0; mf < 4; mf++)
#pragma unroll
        for (int nf = 0; nf < 4; nf++)
#pragma unroll
            for (int i = 0; i < 4; i++) { acch[mf][nf][i] = 0; accm[mf][nf][i] = 0; }

    load_stage(0, 0); cpa_commit();
    load_stage(1, 1); cpa_commit();

    int buf = 0;
    for (int kc = 0; kc < NKC; kc++) {
        // own loads for chunk kc have landed (<=1 group pending = kc+1)
        if (kc < NKC - 1) cpa_wait1(); else cpa_wait0();
        // everyone's chunk-kc loads landed AND everyone finished mma of kc-1
        __syncthreads();
        // refill the buffer freed by chunk kc-1 with chunk kc+2
        if (kc + 2 < NKC) {
            int nb = buf + 2; if (nb >= 3) nb -= 3;
            load_stage(nb, kc + 2);
            cpa_commit();
        }

        const uint32_t st = sb + SM_STAGE + (uint32_t)buf * STAGE_BYTES;
        const uint32_t sA1 = st + OFF_A1, sA2 = st + OFF_A2;
        const uint32_t sB1 = st + OFF_B1, sB2 = st + OFF_B2;

#pragma unroll
        for (int ks = 0; ks < 4; ks++) {
            const uint32_t ko = (uint32_t)(ks * 32);   // +32 s8 per k-step
            uint32_t a1[4][4], a2[4][4];
#pragma unroll
            for (int mf = 0; mf < 4; mf++) {
                ldsm4(a1[mf], sA1 + aoff[mf] + ko);
                ldsm4(a2[mf], sA2 + aoff[mf] + ko);
            }
            uint32_t b1[4][2], b2[4][2];
#pragma unroll
            for (int np = 0; np < 2; np++) {
                uint32_t t[4];
                ldsm4(t, sB1 + boff[np] + ko);
                b1[2 * np][0] = t[0]; b1[2 * np][1] = t[1];
                b1[2 * np + 1][0] = t[2]; b1[2 * np + 1][1] = t[3];
                ldsm4(t, sB2 + boff[np] + ko);
                b2[2 * np][0] = t[0]; b2[2 * np][1] = t[1];
                b2[2 * np + 1][0] = t[2]; b2[2 * np + 1][1] = t[3];
            }
#pragma unroll
            for (int mf = 0; mf < 4; mf++)
#pragma unroll
                for (int nf = 0; nf < 4; nf++) {
                    imma(acch[mf][nf], a1[mf], b1[nf]);
                    imma(accm[mf][nf], a1[mf], b2[nf]);
                    imma(accm[mf][nf], a2[mf], b1[nf]);
                }
        }
        buf = buf + 1; if (buf >= 3) buf = 0;
    }
    __syncthreads();   // all warps done reading stages before epilogue reuses them

    // -------- epilogue: raw = 16384*hi + 128*mid staged in smem; GroupNorm per row --------
    float* ep = reinterpret_cast<float*>(smem + SM_STAGE);
    {
        const int r0 = wr * 64 + (lane >> 2);
        const int c0 = wc * 32 + (lane & 3) * 2;
#pragma unroll
        for (int mf = 0; mf < 4; mf++)
#pragma unroll
            for (int nf = 0; nf < 4; nf++) {
                const int r = r0 + mf * 16;
                const int c = c0 + nf * 8;
                float2 v0, v1;
                v0.x = fmaf(16384.f, (float)acch[mf][nf][0], 128.f * (float)accm[mf][nf][0]);
                v0.y = fmaf(16384.f, (float)acch[mf][nf][1], 128.f * (float)accm[mf][nf][1]);
                v1.x = fmaf(16384.f, (float)acch[mf][nf][2], 128.f * (float)accm[mf][nf][2]);
                v1.y = fmaf(16384.f, (float)acch[mf][nf][3], 128.f * (float)accm[mf][nf][3]);
                *reinterpret_cast<float2*>(ep + (size_t)r * EPS_LD + c) = v0;
                *reinterpret_cast<float2*>(ep + (size_t)(r + 8) * EPS_LD + c) = v1;
            }
    }
    __syncthreads();

    if (tid < BM) {
        const float sAr = g_sA[m0 + tid];
        const float4* row = reinterpret_cast<const float4*>(ep + (size_t)tid * EPS_LD);
        const float4* sb4 = reinterpret_cast<const float4*>(sbias);
        const float4* sc4 = reinterpret_cast<const float4*>(ssb);
        float sum = 0.f, sq = 0.f;
#pragma unroll
        for (int i = 0; i < 32; i++) {
            float4 v = row[i];
            float4 s = sc4[i];
            float4 b = sb4[i];
            float f0 = fmaf(sAr * s.x, v.x, b.x);
            float f1 = fmaf(sAr * s.y, v.y, b.y);
            float f2 = fmaf(sAr * s.z, v.z, b.z);
            float f3 = fmaf(sAr * s.w, v.w, b.w);
            sum += f0 + f1 + f2 + f3;
            sq += f0 * f0 + f1 * f1 + f2 * f2 + f3 * f3;
        }
        const float mean = sum * (1.0f / 128.0f);
        const float rstd = rsqrtf(sq * (1.0f / 128.0f) - mean * mean + EPS);
        float4* po = reinterpret_cast<float4*>(out + (size_t)(m0 + tid) * Ndim + n0);
#pragma unroll
        for (int i = 0; i < 32; i++) {
            float4 v = row[i];
            float4 s = sc4[i];
            float4 b = sb4[i];
            float4 o;
            o.x = fminf(fmaxf((fmaf(sAr * s.x, v.x, b.x) - mean) * rstd, -1.f), 1.f);
            o.y = fminf(fmaxf((fmaf(sAr * s.y, v.y, b.y) - mean) * rstd, -1.f), 1.f);
            o.z = fminf(fmaxf((fmaf(sAr * s.z, v.z, b.z) - mean) * rstd, -1.f), 1.f);
            o.w = fminf(fmaxf((fmaf(sAr * s.w, v.w, b.w) - mean) * rstd, -1.f), 1.f);
            po[i] = o;
        }
    }
}

extern "C" void kernel_launch(void* const* d_in, const int* in_sizes, int n_in,
                              void* d_out, int out_size) {
    const float* x = (const float*)d_in[0];
    const float* wgt = (const float*)d_in[1];
    const float* bias = (const float*)d_in[2];
    float* out = (float*)d_out;

    cudaFuncSetAttribute(gemm_gn_kernel, cudaFuncAttributeMaxDynamicSharedMemorySize,
                         (int)SMEM_TOTAL);

    quant_AB_kernel<<<Mdim + Ndim, 256>>>((const float4*)x, (const float4*)wgt);

    dim3 grid(Ndim / BN, Mdim / BM);   // (32, 64), x-fastest -> B set L2-resident
    gemm_gn_kernel<<<grid, NT, SMEM_TOTAL>>>(bias, out);
}

// round 8
// speedup vs baseline: 1.1241x; 1.0904x over previous
#include <cuda_runtime.h>
#include <cstdint>

#define DEVI __device__ __forceinline__

static constexpr int Mdim = 8192;
static constexpr int Ndim = 4096;
static constexpr int Kdim = 2048;
static constexpr int BM = 128;
static constexpr int BN = 128;
static constexpr int BK = 128;                 // s8 elements (=bytes) per stage chunk
static constexpr int NKC = Kdim / BK;          // 16
static constexpr int NT = 256;                 // 8 warps: 2 (M) x 4 (N)
static constexpr float EPS = 1e-5f;

// smem: [0,1024): sbias(128f) + ssb(128f) ; 3 stages follow
static constexpr unsigned SM_STAGE = 1024;
static constexpr unsigned ROWP = 144;                       // padded row bytes (128B data)
static constexpr unsigned REG_BYTES = 128u * ROWP;          // 18432 per tensor region
static constexpr unsigned OFF_A1 = 0;
static constexpr unsigned OFF_A2 = 1 * REG_BYTES;
static constexpr unsigned OFF_B1 = 2 * REG_BYTES;
static constexpr unsigned OFF_B2 = 3 * REG_BYTES;
static constexpr unsigned STAGE_BYTES = 4 * REG_BYTES;      // 73728
static constexpr unsigned SMEM_TOTAL = SM_STAGE + 3 * STAGE_BYTES;  // 222208
static constexpr int EPS_LD = 132;                          // epilogue row stride (floats)

// quantized operands + per-row scales
__device__ __align__(128) int8_t g_A1[(size_t)Mdim * Kdim];
__device__ __align__(128) int8_t g_A2[(size_t)Mdim * Kdim];
__device__ __align__(128) int8_t g_B1[(size_t)Ndim * Kdim];
__device__ __align__(128) int8_t g_B2[(size_t)Ndim * Kdim];
__device__ float g_sA[Mdim];
__device__ float g_sB[Ndim];

DEVI uint32_t smem_u32(const void* p) {
    uint32_t a;
    asm("{ .reg .u64 t; cvta.to.shared.u64 t, %1; cvt.u32.u64 %0, t; }" : "=r"(a) : "l"(p));
    return a;
}
DEVI void cpa16(uint32_t dst, const void* src) {
    asm volatile("cp.async.cg.shared.global [%0], [%1], 16;\n" :: "r"(dst), "l"(src));
}
DEVI void cpa_commit() { asm volatile("cp.async.commit_group;\n" ::: "memory"); }
DEVI void cpa_wait0()  { asm volatile("cp.async.wait_group 0;\n" ::: "memory"); }
DEVI void cpa_wait1()  { asm volatile("cp.async.wait_group 1;\n" ::: "memory"); }

DEVI void ldsm4(uint32_t (&r)[4], uint32_t addr) {
    asm volatile("ldmatrix.sync.aligned.m8n8.x4.shared.b16 {%0,%1,%2,%3}, [%4];"
                 : "=r"(r[0]), "=r"(r[1]), "=r"(r[2]), "=r"(r[3]) : "r"(addr));
}
DEVI void imma(int (&c)[4], const uint32_t (&a)[4], const uint32_t* b) {
    asm volatile(
        "mma.sync.aligned.m16n8k32.row.col.s32.s8.s8.s32 "
        "{%0,%1,%2,%3}, {%4,%5,%6,%7}, {%8,%9}, {%0,%1,%2,%3};"
        : "+r"(c[0]), "+r"(c[1]), "+r"(c[2]), "+r"(c[3])
        : "r"(a[0]), "r"(a[1]), "r"(a[2]), "r"(a[3]), "r"(b[0]), "r"(b[1]));
}

// ---------------- fp32 -> int8 pair quantization (per-row scale) ----------------
DEVI int pack4(int a, int b, int c, int d) {
    return (a & 0xFF) | ((b & 0xFF) << 8) | ((c & 0xFF) << 16) | ((d & 0xFF) << 24);
}
DEVI void qsplit(float x, float inv, int& h, int& l) {
    float q = x * inv;                          // in [-16256, 16256]
    float x1 = rintf(q * 0.0078125f);           // round(q/128) in [-127,127]
    float x2 = rintf(fmaf(-128.f, x1, q));      // in [-64,64]
    h = (int)x1; l = (int)x2;
}

DEVI void quant_row(const float4* __restrict__ src, int row, int* __restrict__ q1,
                    int* __restrict__ q2, float* __restrict__ sc) {
    __shared__ float red[8];
    const int tid = threadIdx.x;
    const float4* rp = src + (size_t)row * (Kdim / 4);
    float4 v0 = rp[tid];
    float4 v1 = rp[tid + 256];
    float m = fmaxf(fmaxf(fabsf(v0.x), fabsf(v0.y)), fmaxf(fabsf(v0.z), fabsf(v0.w)));
    m = fmaxf(m, fmaxf(fmaxf(fabsf(v1.x), fabsf(v1.y)), fmaxf(fabsf(v1.z), fabsf(v1.w))));
#pragma unroll
    for (int off = 16; off > 0; off >>= 1)
        m = fmaxf(m, __shfl_xor_sync(0xFFFFFFFFu, m, off));
    if ((tid & 31) == 0) red[tid >> 5] = m;
    __syncthreads();
    float rmax = red[0];
#pragma unroll
    for (int i = 1; i < 8; i++) rmax = fmaxf(rmax, red[i]);

    const float sA = rmax > 0.f ? rmax * (1.0f / 16256.0f) : 1.0f;
    if (tid == 0) sc[row] = sA;
    const float inv = 1.0f / sA;

    int h0, l0, h1, l1, h2, l2, h3, l3;
    qsplit(v0.x, inv, h0, l0); qsplit(v0.y, inv, h1, l1);
    qsplit(v0.z, inv, h2, l2); qsplit(v0.w, inv, h3, l3);
    q1[(size_t)row * (Kdim / 4) + tid] = pack4(h0, h1, h2, h3);
    q2[(size_t)row * (Kdim / 4) + tid] = pack4(l0, l1, l2, l3);
    qsplit(v1.x, inv, h0, l0); qsplit(v1.y, inv, h1, l1);
    qsplit(v1.z, inv, h2, l2); qsplit(v1.w, inv, h3, l3);
    q1[(size_t)row * (Kdim / 4) + tid + 256] = pack4(h0, h1, h2, h3);
    q2[(size_t)row * (Kdim / 4) + tid + 256] = pack4(l0, l1, l2, l3);
}

// merged: blocks [0,Mdim) quantize A rows, [Mdim,Mdim+Ndim) quantize B rows
__global__ void __launch_bounds__(256) quant_AB_kernel(const float4* __restrict__ x,
                                                       const float4* __restrict__ wgt) {
    const int b = blockIdx.x;
    if (b < Mdim) {
        quant_row(x, b, reinterpret_cast<int*>(g_A1), reinterpret_cast<int*>(g_A2), g_sA);
    } else {
        quant_row(wgt, b - Mdim, reinterpret_cast<int*>(g_B1), reinterpret_cast<int*>(g_B2), g_sB);
    }
}

// ---------------- fused int8x3 GEMM + scale + bias + GroupNorm + hardtanh ----------------
__global__ void __launch_bounds__(NT, 1)
gemm_gn_kernel(const float* __restrict__ bias, float* __restrict__ out) {
    extern __shared__ __align__(16) char smem[];
    const uint32_t sb = smem_u32(smem);
    const int tid = threadIdx.x;
    const int lane = tid & 31;
    const int w = tid >> 5;
    const int wr = w >> 2;            // 0..1  (M)
    const int wc = w & 3;             // 0..3  (N)
    const int m0 = blockIdx.y * BM;
    const int n0 = blockIdx.x * BN;

    float* sbias = reinterpret_cast<float*>(smem);            // [0,128)
    float* ssb = reinterpret_cast<float*>(smem) + 128;        // [128,256)
    if (tid < BN) {
        sbias[tid] = bias[n0 + tid];
        ssb[tid] = g_sB[n0 + tid];
    }

    // ldmatrix offsets (bytes, relative to region base)
    uint32_t aoff[4];
#pragma unroll
    for (int mf = 0; mf < 4; mf++)
        aoff[mf] = (uint32_t)((wr * 64 + mf * 16 + (lane & 15)) * ROWP + (lane >> 4) * 16);
    uint32_t boff[2];
    {
        int brow = wc * 32 + (lane & 7) + ((lane >> 4) << 3);
        boff[0] = (uint32_t)(brow * ROWP + ((lane >> 3) & 1) * 16);
        boff[1] = (uint32_t)((brow + 16) * ROWP + ((lane >> 3) & 1) * 16);
    }

    const char* pA1 = reinterpret_cast<const char*>(g_A1) + (size_t)m0 * Kdim;
    const char* pA2 = reinterpret_cast<const char*>(g_A2) + (size_t)m0 * Kdim;
    const char* pB1 = reinterpret_cast<const char*>(g_B1) + (size_t)n0 * Kdim;
    const char* pB2 = reinterpret_cast<const char*>(g_B2) + (size_t)n0 * Kdim;

    auto load_stage = [&](int buf, int kc) {
        const uint32_t st = sb + SM_STAGE + (uint32_t)buf * STAGE_BYTES;
        const int k0 = kc * BK;                       // byte offset along K
        const char* bases[4] = {pA1, pA2, pB1, pB2};
#pragma unroll
        for (int r4 = 0; r4 < 4; r4++) {
            const uint32_t dst0 = st + (uint32_t)r4 * REG_BYTES;
#pragma unroll
            for (int q = 0; q < 4; q++) {
                int idx = tid + q * NT;               // 0..1023
                int row = idx >> 3;
                int cc = (idx & 7) * 16;
                cpa16(dst0 + (uint32_t)(row * (int)ROWP + cc),
                      bases[r4] + (size_t)row * Kdim + (size_t)(k0 + cc));
            }
        }
    };

    int acch[4][4][4];   // x1*y1
    int accm[4][4][4];   // x1*y2 + x2*y1
#pragma unroll
    for (int mf = 0; mf < 4; mf++)
#pragma unroll
        for (int nf = 0; nf < 4; nf++)
#pragma unroll
            for (int i = 0; i < 4; i++) { acch[mf][nf][i] = 0; accm[mf][nf][i] = 0; }

    load_stage(0, 0); cpa_commit();
    load_stage(1, 1); cpa_commit();

    int buf = 0;
    for (int kc = 0; kc < NKC; kc++) {
        // own loads for chunk kc have landed (<=1 group pending = kc+1)
        if (kc < NKC - 1) cpa_wait1(); else cpa_wait0();
        // everyone's chunk-kc loads landed AND everyone finished mma of kc-1
        __syncthreads();

        const uint32_t st = sb + SM_STAGE + (uint32_t)buf * STAGE_BYTES;
        const uint32_t sA1 = st + OFF_A1, sA2 = st + OFF_A2;
        const uint32_t sB1 = st + OFF_B1, sB2 = st + OFF_B2;

#pragma unroll
        for (int ks = 0; ks < 4; ks++) {
            const uint32_t ko = (uint32_t)(ks * 32);   // +32 s8 per k-step
            // B fragments for this ks (8 ldsm)
            uint32_t b1[4][2], b2[4][2];
#pragma unroll
            for (int np = 0; np < 2; np++) {
                uint32_t t[4];
                ldsm4(t, sB1 + boff[np] + ko);
                b1[2 * np][0] = t[0]; b1[2 * np][1] = t[1];
                b1[2 * np + 1][0] = t[2]; b1[2 * np + 1][1] = t[3];
                ldsm4(t, sB2 + boff[np] + ko);
                b2[2 * np][0] = t[0]; b2[2 * np][1] = t[1];
                b2[2 * np + 1][0] = t[2]; b2[2 * np + 1][1] = t[3];
            }
            // per-mf: 2 ldsm then 12 imma -> mf+1 loads overlap mf's imma tail
#pragma unroll
            for (int mf = 0; mf < 4; mf++) {
                uint32_t a1[4], a2[4];
                ldsm4(a1, sA1 + aoff[mf] + ko);
                ldsm4(a2, sA2 + aoff[mf] + ko);
#pragma unroll
                for (int nf = 0; nf < 4; nf++) imma(acch[mf][nf], a1, b1[nf]);
#pragma unroll
                for (int nf = 0; nf < 4; nf++) imma(accm[mf][nf], a1, b2[nf]);
#pragma unroll
                for (int nf = 0; nf < 4; nf++) imma(accm[mf][nf], a2, b1[nf]);
            }
            // issue the stage prefetch AFTER the first ks so fragment loads
            // hit the LSU immediately post-barrier; DMA still has ~2 chunks slack
            if (ks == 0 && kc + 2 < NKC) {
                int nb = buf + 2; if (nb >= 3) nb -= 3;
                load_stage(nb, kc + 2);
                cpa_commit();
            }
        }
        buf = buf + 1; if (buf >= 3) buf = 0;
    }
    __syncthreads();   // all warps done reading stages before epilogue reuses them

    // -------- epilogue: raw = 16384*hi + 128*mid staged in smem; GroupNorm per row --------
    float* ep = reinterpret_cast<float*>(smem + SM_STAGE);
    {
        const int r0 = wr * 64 + (lane >> 2);
        const int c0 = wc * 32 + (lane & 3) * 2;
#pragma unroll
        for (int mf = 0; mf < 4; mf++)
#pragma unroll
            for (int nf = 0; nf < 4; nf++) {
                const int r = r0 + mf * 16;
                const int c = c0 + nf * 8;
                float2 v0, v1;
                v0.x = fmaf(16384.f, (float)acch[mf][nf][0], 128.f * (float)accm[mf][nf][0]);
                v0.y = fmaf(16384.f, (float)acch[mf][nf][1], 128.f * (float)accm[mf][nf][1]);
                v1.x = fmaf(16384.f, (float)acch[mf][nf][2], 128.f * (float)accm[mf][nf][2]);
                v1.y = fmaf(16384.f, (float)acch[mf][nf][3], 128.f * (float)accm[mf][nf][3]);
                *reinterpret_cast<float2*>(ep + (size_t)r * EPS_LD + c) = v0;
                *reinterpret_cast<float2*>(ep + (size_t)(r + 8) * EPS_LD + c) = v1;
            }
    }
    __syncthreads();

    if (tid < BM) {
        const float sAr = g_sA[m0 + tid];
        const float4* row = reinterpret_cast<const float4*>(ep + (size_t)tid * EPS_LD);
        const float4* sb4 = reinterpret_cast<const float4*>(sbias);
        const float4* sc4 = reinterpret_cast<const float4*>(ssb);
        float sum = 0.f, sq = 0.f;
#pragma unroll
        for (int i = 0; i < 32; i++) {
            float4 v = row[i];
            float4 s = sc4[i];
            float4 b = sb4[i];
            float f0 = fmaf(sAr * s.x, v.x, b.x);
            float f1 = fmaf(sAr * s.y, v.y, b.y);
            float f2 = fmaf(sAr * s.z, v.z, b.z);
            float f3 = fmaf(sAr * s.w, v.w, b.w);
            sum += f0 + f1 + f2 + f3;
            sq += f0 * f0 + f1 * f1 + f2 * f2 + f3 * f3;
        }
        const float mean = sum * (1.0f / 128.0f);
        const float rstd = rsqrtf(sq * (1.0f / 128.0f) - mean * mean + EPS);
        float4* po = reinterpret_cast<float4*>(out + (size_t)(m0 + tid) * Ndim + n0);
#pragma unroll
        for (int i = 0; i < 32; i++) {
            float4 v = row[i];
            float4 s = sc4[i];
            float4 b = sb4[i];
            float4 o;
            o.x = fminf(fmaxf((fmaf(sAr * s.x, v.x, b.x) - mean) * rstd, -1.f), 1.f);
            o.y = fminf(fmaxf((fmaf(sAr * s.y, v.y, b.y) - mean) * rstd, -1.f), 1.f);
            o.z = fminf(fmaxf((fmaf(sAr * s.z, v.z, b.z) - mean) * rstd, -1.f), 1.f);
            o.w = fminf(fmaxf((fmaf(sAr * s.w, v.w, b.w) - mean) * rstd, -1.f), 1.f);
            po[i] = o;
        }
    }
}

extern "C" void kernel_launch(void* const* d_in, const int* in_sizes, int n_in,
                              void* d_out, int out_size) {
    const float* x = (const float*)d_in[0];
    const float* wgt = (const float*)d_in[1];
    const float* bias = (const float*)d_in[2];
    float* out = (float*)d_out;

    cudaFuncSetAttribute(gemm_gn_kernel, cudaFuncAttributeMaxDynamicSharedMemorySize,
                         (int)SMEM_TOTAL);

    quant_AB_kernel<<<Mdim + Ndim, 256>>>((const float4*)x, (const float4*)wgt);

    dim3 grid(Ndim / BN, Mdim / BM);   // (32, 64), x-fastest -> B set L2-resident
    gemm_gn_kernel<<<grid, NT, SMEM_TOTAL>>>(bias, out);
}

// round 11
// speedup vs baseline: 1.1510x; 1.0239x over previous
#include <cuda_runtime.h>
#include <cstdint>

#define DEVI __device__ __forceinline__

static constexpr int Mdim = 8192;
static constexpr int Ndim = 4096;
static constexpr int Kdim = 2048;
static constexpr int BM = 128;
static constexpr int BN = 128;
static constexpr int BK = 128;                 // s8 elements (=bytes) per stage chunk
static constexpr int NKC = Kdim / BK;          // 16
static constexpr int NT = 256;                 // 8 warps: 2 (M) x 4 (N)
static constexpr float EPS = 1e-5f;

// smem: [0,1024): sbias(128f) + ssb(128f) ; 3 stages follow
static constexpr unsigned SM_STAGE = 1024;
static constexpr unsigned ROWP = 144;                       // padded row bytes (128B data)
static constexpr unsigned REG_BYTES = 128u * ROWP;          // 18432 per tensor region
static constexpr unsigned OFF_A1 = 0;
static constexpr unsigned OFF_A2 = 1 * REG_BYTES;
static constexpr unsigned OFF_B1 = 2 * REG_BYTES;
static constexpr unsigned OFF_B2 = 3 * REG_BYTES;
static constexpr unsigned STAGE_BYTES = 4 * REG_BYTES;      // 73728
static constexpr unsigned SMEM_TOTAL = SM_STAGE + 3 * STAGE_BYTES;  // 222208
static constexpr int EPS_LD = 132;                          // epilogue row stride (floats)

// quantized operands + per-row scales
__device__ __align__(128) int8_t g_A1[(size_t)Mdim * Kdim];
__device__ __align__(128) int8_t g_A2[(size_t)Mdim * Kdim];
__device__ __align__(128) int8_t g_B1[(size_t)Ndim * Kdim];
__device__ __align__(128) int8_t g_B2[(size_t)Ndim * Kdim];
__device__ float g_sA[Mdim];
__device__ float g_sB[Ndim];

DEVI uint32_t smem_u32(const void* p) {
    uint32_t a;
    asm("{ .reg .u64 t; cvta.to.shared.u64 t, %1; cvt.u32.u64 %0, t; }" : "=r"(a) : "l"(p));
    return a;
}
DEVI void cpa16(uint32_t dst, const void* src) {
    asm volatile("cp.async.cg.shared.global [%0], [%1], 16;\n" :: "r"(dst), "l"(src));
}
DEVI void cpa_commit() { asm volatile("cp.async.commit_group;\n" ::: "memory"); }
DEVI void cpa_wait0()  { asm volatile("cp.async.wait_group 0;\n" ::: "memory"); }

DEVI void ldsm4(uint32_t (&r)[4], uint32_t addr) {
    asm volatile("ldmatrix.sync.aligned.m8n8.x4.shared.b16 {%0,%1,%2,%3}, [%4];"
                 : "=r"(r[0]), "=r"(r[1]), "=r"(r[2]), "=r"(r[3]) : "r"(addr));
}
// load one ldsm4 into B fragment pair [2*np], [2*np+1]
DEVI void ldB(uint32_t (&bf)[4][2], int np, uint32_t addr) {
    uint32_t t[4];
    ldsm4(t, addr);
    bf[2 * np][0] = t[0]; bf[2 * np][1] = t[1];
    bf[2 * np + 1][0] = t[2]; bf[2 * np + 1][1] = t[3];
}
DEVI void imma(int (&c)[4], const uint32_t (&a)[4], const uint32_t* b) {
    asm volatile(
        "mma.sync.aligned.m16n8k32.row.col.s32.s8.s8.s32 "
        "{%0,%1,%2,%3}, {%4,%5,%6,%7}, {%8,%9}, {%0,%1,%2,%3};"
        : "+r"(c[0]), "+r"(c[1]), "+r"(c[2]), "+r"(c[3])
        : "r"(a[0]), "r"(a[1]), "r"(a[2]), "r"(a[3]), "r"(b[0]), "r"(b[1]));
}

// ---------------- fp32 -> int8 pair quantization (per-row scale) ----------------
DEVI int pack4(int a, int b, int c, int d) {
    return (a & 0xFF) | ((b & 0xFF) << 8) | ((c & 0xFF) << 16) | ((d & 0xFF) << 24);
}
DEVI void qsplit(float x, float inv, int& h, int& l) {
    float q = x * inv;                          // in [-16256, 16256]
    float x1 = rintf(q * 0.0078125f);           // round(q/128) in [-127,127]
    float x2 = rintf(fmaf(-128.f, x1, q));      // in [-64,64]
    h = (int)x1; l = (int)x2;
}

DEVI void quant_row(const float4* __restrict__ src, int row, int* __restrict__ q1,
                    int* __restrict__ q2, float* __restrict__ sc) {
    __shared__ float red[8];
    const int tid = threadIdx.x;
    const float4* rp = src + (size_t)row * (Kdim / 4);
    float4 v0 = rp[tid];
    float4 v1 = rp[tid + 256];
    float m = fmaxf(fmaxf(fabsf(v0.x), fabsf(v0.y)), fmaxf(fabsf(v0.z), fabsf(v0.w)));
    m = fmaxf(m, fmaxf(fmaxf(fabsf(v1.x), fabsf(v1.y)), fmaxf(fabsf(v1.z), fabsf(v1.w))));
#pragma unroll
    for (int off = 16; off > 0; off >>= 1)
        m = fmaxf(m, __shfl_xor_sync(0xFFFFFFFFu, m, off));
    if ((tid & 31) == 0) red[tid >> 5] = m;
    __syncthreads();
    float rmax = red[0];
#pragma unroll
    for (int i = 1; i < 8; i++) rmax = fmaxf(rmax, red[i]);

    const float sA = rmax > 0.f ? rmax * (1.0f / 16256.0f) : 1.0f;
    if (tid == 0) sc[row] = sA;
    const float inv = 1.0f / sA;

    int h0, l0, h1, l1, h2, l2, h3, l3;
    qsplit(v0.x, inv, h0, l0); qsplit(v0.y, inv, h1, l1);
    qsplit(v0.z, inv, h2, l2); qsplit(v0.w, inv, h3, l3);
    q1[(size_t)row * (Kdim / 4) + tid] = pack4(h0, h1, h2, h3);
    q2[(size_t)row * (Kdim / 4) + tid] = pack4(l0, l1, l2, l3);
    qsplit(v1.x, inv, h0, l0); qsplit(v1.y, inv, h1, l1);
    qsplit(v1.z, inv, h2, l2); qsplit(v1.w, inv, h3, l3);
    q1[(size_t)row * (Kdim / 4) + tid + 256] = pack4(h0, h1, h2, h3);
    q2[(size_t)row * (Kdim / 4) + tid + 256] = pack4(l0, l1, l2, l3);
}

// merged: blocks [0,Mdim) quantize A rows, [Mdim,Mdim+Ndim) quantize B rows
__global__ void __launch_bounds__(256) quant_AB_kernel(const float4* __restrict__ x,
                                                       const float4* __restrict__ wgt) {
    const int b = blockIdx.x;
    if (b < Mdim) {
        quant_row(x, b, reinterpret_cast<int*>(g_A1), reinterpret_cast<int*>(g_A2), g_sA);
    } else {
        quant_row(wgt, b - Mdim, reinterpret_cast<int*>(g_B1), reinterpret_cast<int*>(g_B2), g_sB);
    }
}

// ---------------- fused int8x3 GEMM + scale + bias + GroupNorm + hardtanh ----------------
__global__ void __launch_bounds__(NT, 1)
gemm_gn_kernel(const float* __restrict__ bias, float* __restrict__ out) {
    extern __shared__ __align__(16) char smem[];
    const uint32_t sb = smem_u32(smem);
    const int tid = threadIdx.x;
    const int lane = tid & 31;
    const int w = tid >> 5;
    const int wr = w >> 2;            // 0..1  (M)
    const int wc = w & 3;             // 0..3  (N)
    const int m0 = blockIdx.y * BM;
    const int n0 = blockIdx.x * BN;

    float* sbias = reinterpret_cast<float*>(smem);            // [0,128)
    float* ssb = reinterpret_cast<float*>(smem) + 128;        // [128,256)
    if (tid < BN) {
        sbias[tid] = bias[n0 + tid];
        ssb[tid] = g_sB[n0 + tid];
    }

    // ldmatrix offsets (bytes, relative to region base)
    uint32_t aoff[4];
#pragma unroll
    for (int mf = 0; mf < 4; mf++)
        aoff[mf] = (uint32_t)((wr * 64 + mf * 16 + (lane & 15)) * ROWP + (lane >> 4) * 16);
    uint32_t boff[2];
    {
        int brow = wc * 32 + (lane & 7) + ((lane >> 4) << 3);
        boff[0] = (uint32_t)(brow * ROWP + ((lane >> 3) & 1) * 16);
        boff[1] = (uint32_t)((brow + 16) * ROWP + ((lane >> 3) & 1) * 16);
    }

    const char* pA1 = reinterpret_cast<const char*>(g_A1) + (size_t)m0 * Kdim;
    const char* pA2 = reinterpret_cast<const char*>(g_A2) + (size_t)m0 * Kdim;
    const char* pB1 = reinterpret_cast<const char*>(g_B1) + (size_t)n0 * Kdim;
    const char* pB2 = reinterpret_cast<const char*>(g_B2) + (size_t)n0 * Kdim;

    auto load_stage = [&](int bf, int kc) {
        const uint32_t st = sb + SM_STAGE + (uint32_t)bf * STAGE_BYTES;
        const int k0 = kc * BK;                       // byte offset along K
        const char* bases[4] = {pA1, pA2, pB1, pB2};
#pragma unroll
        for (int r4 = 0; r4 < 4; r4++) {
            const uint32_t dst0 = st + (uint32_t)r4 * REG_BYTES;
#pragma unroll
            for (int q = 0; q < 4; q++) {
                int idx = tid + q * NT;               // 0..1023
                int row = idx >> 3;
                int cc = (idx & 7) * 16;
                cpa16(dst0 + (uint32_t)(row * (int)ROWP + cc),
                      bases[r4] + (size_t)row * Kdim + (size_t)(k0 + cc));
            }
        }
    };

    int acch[4][4][4];   // x1*y1
    int accm[4][4][4];   // x1*y2 + x2*y1
#pragma unroll
    for (int mf = 0; mf < 4; mf++)
#pragma unroll
        for (int nf = 0; nf < 4; nf++)
#pragma unroll
            for (int i = 0; i < 4; i++) { acch[mf][nf][i] = 0; accm[mf][nf][i] = 0; }

    load_stage(0, 0); cpa_commit();
    load_stage(1, 1); cpa_commit();

    // double-buffered fragments (software pipeline, distance = 1 step = 12 IMMAs)
    uint32_t a1f[2][4], a2f[2][4];
    uint32_t b1[2][4][2], b2[2][4][2];

    // ---- prologue: wait chunk 0+1, fill frags for (kc0, ks0, mf0) ----
    cpa_wait0();
    __syncthreads();
    {
        const uint32_t st = sb + SM_STAGE;
        ldB(b1[0], 0, st + OFF_B1 + boff[0]);
        ldB(b2[0], 0, st + OFF_B2 + boff[0]);
        ldB(b1[0], 1, st + OFF_B1 + boff[1]);
        ldB(b2[0], 1, st + OFF_B2 + boff[1]);
        ldsm4(a1f[0], st + OFF_A1 + aoff[0]);
        ldsm4(a2f[0], st + OFF_A2 + aoff[0]);
    }

    int buf = 0;
    for (int kc = 0; kc < NKC; kc++) {
        if (kc > 0) {      // chunk kc (+ kc+1 when committed) resident after drain
            cpa_wait0();
            __syncthreads();
        }
        const int bufn = (buf + 1 < 3) ? buf + 1 : 0;
        const uint32_t st = sb + SM_STAGE + (uint32_t)buf * STAGE_BYTES;
        const uint32_t stn = sb + SM_STAGE + (uint32_t)bufn * STAGE_BYTES;
        const bool more = (kc + 1 < NKC);

#pragma unroll
        for (int ks = 0; ks < 4; ks++) {
            const int bb = ks & 1;
#pragma unroll
            for (int mf = 0; mf < 4; mf++) {
                const int s = ks * 4 + mf;
                const int ab = s & 1;

                // --- prefetch A frags for step s+1 (consumed 12 IMMAs later) ---
                if (s < 15) {
                    const uint32_t na = aoff[(s + 1) & 3] + (uint32_t)(((s + 1) >> 2) * 32);
                    ldsm4(a1f[ab ^ 1], st + OFF_A1 + na);
                    ldsm4(a2f[ab ^ 1], st + OFF_A2 + na);
                } else if (more) {
                    ldsm4(a1f[ab ^ 1], stn + OFF_A1 + aoff[0]);
                    ldsm4(a2f[ab ^ 1], stn + OFF_A2 + aoff[0]);
                }
                // --- prefetch B frags for next ks, spread over mf=0,1 ---
                if (mf < 2) {
                    const int np = mf;
                    if (ks < 3) {
                        const uint32_t nko = (uint32_t)((ks + 1) * 32);
                        ldB(b1[bb ^ 1], np, st + OFF_B1 + boff[np] + nko);
                        ldB(b2[bb ^ 1], np, st + OFF_B2 + boff[np] + nko);
                    } else if (more) {
                        ldB(b1[bb ^ 1], np, stn + OFF_B1 + boff[np]);
                        ldB(b2[bb ^ 1], np, stn + OFF_B2 + boff[np]);
                    }
                }

                // --- compute step s: 12 IMMAs on fully-resident fragments ---
#pragma unroll
                for (int nf = 0; nf < 4; nf++) imma(acch[mf][nf], a1f[ab], b1[bb][nf]);
#pragma unroll
                for (int nf = 0; nf < 4; nf++) imma(accm[mf][nf], a1f[ab], b2[bb][nf]);
#pragma unroll
                for (int nf = 0; nf < 4; nf++) imma(accm[mf][nf], a2f[ab], b1[bb][nf]);

                // stage prefetch for kc+2 after ks0 (LSU quiet zone)
                if (s == 3 && kc + 2 < NKC) {
                    int nb = buf + 2; if (nb >= 3) nb -= 3;
                    load_stage(nb, kc + 2);
                    cpa_commit();
                }
            }
        }
        buf = bufn;
    }
    __syncthreads();   // all warps done reading stages before epilogue reuses them

    // -------- epilogue: raw = 16384*hi + 128*mid staged in smem; GroupNorm per row --------
    float* ep = reinterpret_cast<float*>(smem + SM_STAGE);
    {
        const int r0 = wr * 64 + (lane >> 2);
        const int c0 = wc * 32 + (lane & 3) * 2;
#pragma unroll
        for (int mf = 0; mf < 4; mf++)
#pragma unroll
            for (int nf = 0; nf < 4; nf++) {
                const int r = r0 + mf * 16;
                const int c = c0 + nf * 8;
                float2 v0, v1;
                v0.x = fmaf(16384.f, (float)acch[mf][nf][0], 128.f * (float)accm[mf][nf][0]);
                v0.y = fmaf(16384.f, (float)acch[mf][nf][1], 128.f * (float)accm[mf][nf][1]);
                v1.x = fmaf(16384.f, (float)acch[mf][nf][2], 128.f * (float)accm[mf][nf][2]);
                v1.y = fmaf(16384.f, (float)acch[mf][nf][3], 128.f * (float)accm[mf][nf][3]);
                *reinterpret_cast<float2*>(ep + (size_t)r * EPS_LD + c) = v0;
                *reinterpret_cast<float2*>(ep + (size_t)(r + 8) * EPS_LD + c) = v1;
            }
    }
    __syncthreads();

    if (tid < BM) {
        const float sAr = g_sA[m0 + tid];
        const float4* row = reinterpret_cast<const float4*>(ep + (size_t)tid * EPS_LD);
        const float4* sb4 = reinterpret_cast<const float4*>(sbias);
        const float4* sc4 = reinterpret_cast<const float4*>(ssb);
        float sum = 0.f, sq = 0.f;
#pragma unroll
        for (int i = 0; i < 32; i++) {
            float4 v = row[i];
            float4 s = sc4[i];
            float4 b = sb4[i];
            float f0 = fmaf(sAr * s.x, v.x, b.x);
            float f1 = fmaf(sAr * s.y, v.y, b.y);
            float f2 = fmaf(sAr * s.z, v.z, b.z);
            float f3 = fmaf(sAr * s.w, v.w, b.w);
            sum += f0 + f1 + f2 + f3;
            sq += f0 * f0 + f1 * f1 + f2 * f2 + f3 * f3;
        }
        const float mean = sum * (1.0f / 128.0f);
        const float rstd = rsqrtf(sq * (1.0f / 128.0f) - mean * mean + EPS);
        float4* po = reinterpret_cast<float4*>(out + (size_t)(m0 + tid) * Ndim + n0);
#pragma unroll
        for (int i = 0; i < 32; i++) {
            float4 v = row[i];
            float4 s = sc4[i];
            float4 b = sb4[i];
            float4 o;
            o.x = fminf(fmaxf((fmaf(sAr * s.x, v.x, b.x) - mean) * rstd, -1.f), 1.f);
            o.y = fminf(fmaxf((fmaf(sAr * s.y, v.y, b.y) - mean) * rstd, -1.f), 1.f);
            o.z = fminf(fmaxf((fmaf(sAr * s.z, v.z, b.z) - mean) * rstd, -1.f), 1.f);
            o.w = fminf(fmaxf((fmaf(sAr * s.w, v.w, b.w) - mean) * rstd, -1.f), 1.f);
            po[i] = o;
        }
    }
}

extern "C" void kernel_launch(void* const* d_in, const int* in_sizes, int n_in,
                              void* d_out, int out_size) {
    const float* x = (const float*)d_in[0];
    const float* wgt = (const float*)d_in[1];
    const float* bias = (const float*)d_in[2];
    float* out = (float*)d_out;

    cudaFuncSetAttribute(gemm_gn_kernel, cudaFuncAttributeMaxDynamicSharedMemorySize,
                         (int)SMEM_TOTAL);

    quant_AB_kernel<<<Mdim + Ndim, 256>>>((const float4*)x, (const float4*)wgt);

    dim3 grid(Ndim / BN, Mdim / BM);   // (32, 64), x-fastest -> B set L2-resident
    gemm_gn_kernel<<<grid, NT, SMEM_TOTAL>>>(bias, out);
}

// round 12
// speedup vs baseline: 1.2177x; 1.0579x over previous
#include <cuda_runtime.h>
#include <cstdint>

#define DEVI __device__ __forceinline__

static constexpr int Mdim = 8192;
static constexpr int Ndim = 4096;
static constexpr int Kdim = 2048;
static constexpr int BM = 128;
static constexpr int BN = 128;
static constexpr int BK = 128;                 // s8 elements (=bytes) per stage chunk
static constexpr int NKC = Kdim / BK;          // 16
static constexpr int NT = 512;                 // 16 warps: 4 (M) x 4 (N)
static constexpr float EPS = 1e-5f;

// smem: [0,1024): sbias(128f) + ssb(128f) ; 3 stages follow
static constexpr unsigned SM_STAGE = 1024;
static constexpr unsigned ROWP = 144;                       // padded row bytes (128B data)
static constexpr unsigned REG_BYTES = 128u * ROWP;          // 18432 per tensor region
static constexpr unsigned OFF_A1 = 0;
static constexpr unsigned OFF_A2 = 1 * REG_BYTES;
static constexpr unsigned OFF_B1 = 2 * REG_BYTES;
static constexpr unsigned OFF_B2 = 3 * REG_BYTES;
static constexpr unsigned STAGE_BYTES = 4 * REG_BYTES;      // 73728
static constexpr unsigned SMEM_TOTAL = SM_STAGE + 3 * STAGE_BYTES;  // 222208
static constexpr int EPS_LD = 132;                          // epilogue row stride (floats)

// quantized operands + per-row scales
__device__ __align__(128) int8_t g_A1[(size_t)Mdim * Kdim];
__device__ __align__(128) int8_t g_A2[(size_t)Mdim * Kdim];
__device__ __align__(128) int8_t g_B1[(size_t)Ndim * Kdim];
__device__ __align__(128) int8_t g_B2[(size_t)Ndim * Kdim];
__device__ float g_sA[Mdim];
__device__ float g_sB[Ndim];

DEVI uint32_t smem_u32(const void* p) {
    uint32_t a;
    asm("{ .reg .u64 t; cvta.to.shared.u64 t, %1; cvt.u32.u64 %0, t; }" : "=r"(a) : "l"(p));
    return a;
}
DEVI void cpa16(uint32_t dst, const void* src) {
    asm volatile("cp.async.cg.shared.global [%0], [%1], 16;\n" :: "r"(dst), "l"(src));
}
DEVI void cpa_commit() { asm volatile("cp.async.commit_group;\n" ::: "memory"); }
DEVI void cpa_wait0()  { asm volatile("cp.async.wait_group 0;\n" ::: "memory"); }

DEVI void ldsm4(uint32_t (&r)[4], uint32_t addr) {
    asm volatile("ldmatrix.sync.aligned.m8n8.x4.shared.b16 {%0,%1,%2,%3}, [%4];"
                 : "=r"(r[0]), "=r"(r[1]), "=r"(r[2]), "=r"(r[3]) : "r"(addr));
}
// load one ldsm4 into B fragment pair [2*np], [2*np+1]
DEVI void ldB(uint32_t (&bf)[4][2], int np, uint32_t addr) {
    uint32_t t[4];
    ldsm4(t, addr);
    bf[2 * np][0] = t[0]; bf[2 * np][1] = t[1];
    bf[2 * np + 1][0] = t[2]; bf[2 * np + 1][1] = t[3];
}
DEVI void imma(int (&c)[4], const uint32_t (&a)[4], const uint32_t* b) {
    asm volatile(
        "mma.sync.aligned.m16n8k32.row.col.s32.s8.s8.s32 "
        "{%0,%1,%2,%3}, {%4,%5,%6,%7}, {%8,%9}, {%0,%1,%2,%3};"
        : "+r"(c[0]), "+r"(c[1]), "+r"(c[2]), "+r"(c[3])
        : "r"(a[0]), "r"(a[1]), "r"(a[2]), "r"(a[3]), "r"(b[0]), "r"(b[1]));
}

// ---------------- fp32 -> int8 pair quantization (per-row scale) ----------------
DEVI int pack4(int a, int b, int c, int d) {
    return (a & 0xFF) | ((b & 0xFF) << 8) | ((c & 0xFF) << 16) | ((d & 0xFF) << 24);
}
DEVI void qsplit(float x, float inv, int& h, int& l) {
    float q = x * inv;                          // in [-16256, 16256]
    float x1 = rintf(q * 0.0078125f);           // round(q/128) in [-127,127]
    float x2 = rintf(fmaf(-128.f, x1, q));      // in [-64,64]
    h = (int)x1; l = (int)x2;
}

DEVI void quant_row(const float4* __restrict__ src, int row, int* __restrict__ q1,
                    int* __restrict__ q2, float* __restrict__ sc) {
    __shared__ float red[8];
    const int tid = threadIdx.x;
    const float4* rp = src + (size_t)row * (Kdim / 4);
    float4 v0 = rp[tid];
    float4 v1 = rp[tid + 256];
    float m = fmaxf(fmaxf(fabsf(v0.x), fabsf(v0.y)), fmaxf(fabsf(v0.z), fabsf(v0.w)));
    m = fmaxf(m, fmaxf(fmaxf(fabsf(v1.x), fabsf(v1.y)), fmaxf(fabsf(v1.z), fabsf(v1.w))));
#pragma unroll
    for (int off = 16; off > 0; off >>= 1)
        m = fmaxf(m, __shfl_xor_sync(0xFFFFFFFFu, m, off));
    if ((tid & 31) == 0) red[tid >> 5] = m;
    __syncthreads();
    float rmax = red[0];
#pragma unroll
    for (int i = 1; i < 8; i++) rmax = fmaxf(rmax, red[i]);

    const float sA = rmax > 0.f ? rmax * (1.0f / 16256.0f) : 1.0f;
    if (tid == 0) sc[row] = sA;
    const float inv = 1.0f / sA;

    int h0, l0, h1, l1, h2, l2, h3, l3;
    qsplit(v0.x, inv, h0, l0); qsplit(v0.y, inv, h1, l1);
    qsplit(v0.z, inv, h2, l2); qsplit(v0.w, inv, h3, l3);
    q1[(size_t)row * (Kdim / 4) + tid] = pack4(h0, h1, h2, h3);
    q2[(size_t)row * (Kdim / 4) + tid] = pack4(l0, l1, l2, l3);
    qsplit(v1.x, inv, h0, l0); qsplit(v1.y, inv, h1, l1);
    qsplit(v1.z, inv, h2, l2); qsplit(v1.w, inv, h3, l3);
    q1[(size_t)row * (Kdim / 4) + tid + 256] = pack4(h0, h1, h2, h3);
    q2[(size_t)row * (Kdim / 4) + tid + 256] = pack4(l0, l1, l2, l3);
}

// merged: blocks [0,Mdim) quantize A rows, [Mdim,Mdim+Ndim) quantize B rows
__global__ void __launch_bounds__(256) quant_AB_kernel(const float4* __restrict__ x,
                                                       const float4* __restrict__ wgt) {
    const int b = blockIdx.x;
    if (b < Mdim) {
        quant_row(x, b, reinterpret_cast<int*>(g_A1), reinterpret_cast<int*>(g_A2), g_sA);
    } else {
        quant_row(wgt, b - Mdim, reinterpret_cast<int*>(g_B1), reinterpret_cast<int*>(g_B2), g_sB);
    }
}

// ---------------- fused int8x3 GEMM + scale + bias + GroupNorm + hardtanh ----------------
__global__ void __launch_bounds__(NT, 1)
gemm_gn_kernel(const float* __restrict__ bias, float* __restrict__ out) {
    extern __shared__ __align__(16) char smem[];
    const uint32_t sb = smem_u32(smem);
    const int tid = threadIdx.x;
    const int lane = tid & 31;
    const int w = tid >> 5;           // 0..15
    const int wr = w >> 2;            // 0..3  (M)
    const int wc = w & 3;             // 0..3  (N)
    const int m0 = blockIdx.y * BM;
    const int n0 = blockIdx.x * BN;

    float* sbias = reinterpret_cast<float*>(smem);            // [0,128)
    float* ssb = reinterpret_cast<float*>(smem) + 128;        // [128,256)
    if (tid < BN) {
        sbias[tid] = bias[n0 + tid];
        ssb[tid] = g_sB[n0 + tid];
    }

    // ldmatrix offsets (bytes, relative to region base); warp tile 32x32
    uint32_t aoff[2];
#pragma unroll
    for (int mf = 0; mf < 2; mf++)
        aoff[mf] = (uint32_t)((wr * 32 + mf * 16 + (lane & 15)) * ROWP + (lane >> 4) * 16);
    uint32_t boff[2];
    {
        int brow = wc * 32 + (lane & 7) + ((lane >> 4) << 3);
        boff[0] = (uint32_t)(brow * ROWP + ((lane >> 3) & 1) * 16);
        boff[1] = (uint32_t)((brow + 16) * ROWP + ((lane >> 3) & 1) * 16);
    }

    const char* pA1 = reinterpret_cast<const char*>(g_A1) + (size_t)m0 * Kdim;
    const char* pA2 = reinterpret_cast<const char*>(g_A2) + (size_t)m0 * Kdim;
    const char* pB1 = reinterpret_cast<const char*>(g_B1) + (size_t)n0 * Kdim;
    const char* pB2 = reinterpret_cast<const char*>(g_B2) + (size_t)n0 * Kdim;

    auto load_stage = [&](int bf, int kc) {
        const uint32_t st = sb + SM_STAGE + (uint32_t)bf * STAGE_BYTES;
        const int k0 = kc * BK;                       // byte offset along K
        const char* bases[4] = {pA1, pA2, pB1, pB2};
#pragma unroll
        for (int r4 = 0; r4 < 4; r4++) {
            const uint32_t dst0 = st + (uint32_t)r4 * REG_BYTES;
#pragma unroll
            for (int q = 0; q < 2; q++) {
                int idx = tid + q * NT;               // 0..1023
                int row = idx >> 3;
                int cc = (idx & 7) * 16;
                cpa16(dst0 + (uint32_t)(row * (int)ROWP + cc),
                      bases[r4] + (size_t)row * Kdim + (size_t)(k0 + cc));
            }
        }
    };

    int acch[2][4][4];   // x1*y1
    int accm[2][4][4];   // x1*y2 + x2*y1
#pragma unroll
    for (int mf = 0; mf < 2; mf++)
#pragma unroll
        for (int nf = 0; nf < 4; nf++)
#pragma unroll
            for (int i = 0; i < 4; i++) { acch[mf][nf][i] = 0; accm[mf][nf][i] = 0; }

    load_stage(0, 0); cpa_commit();
    load_stage(1, 1); cpa_commit();

    // double-buffered fragments (software pipeline, distance = 1 step = 12 IMMAs)
    uint32_t a1f[2][4], a2f[2][4];
    uint32_t b1[2][4][2], b2[2][4][2];

    // ---- prologue: wait chunk 0+1, fill frags for (kc0, ks0, mf0) ----
    cpa_wait0();
    __syncthreads();
    {
        const uint32_t st = sb + SM_STAGE;
        ldB(b1[0], 0, st + OFF_B1 + boff[0]);
        ldB(b2[0], 0, st + OFF_B2 + boff[0]);
        ldB(b1[0], 1, st + OFF_B1 + boff[1]);
        ldB(b2[0], 1, st + OFF_B2 + boff[1]);
        ldsm4(a1f[0], st + OFF_A1 + aoff[0]);
        ldsm4(a2f[0], st + OFF_A2 + aoff[0]);
    }

    int buf = 0;
    for (int kc = 0; kc < NKC; kc++) {
        if (kc > 0) {      // chunk kc (+ kc+1 when committed) resident after drain
            cpa_wait0();
            __syncthreads();
        }
        const int bufn = (buf + 1 < 3) ? buf + 1 : 0;
        const uint32_t st = sb + SM_STAGE + (uint32_t)buf * STAGE_BYTES;
        const uint32_t stn = sb + SM_STAGE + (uint32_t)bufn * STAGE_BYTES;
        const bool more = (kc + 1 < NKC);

#pragma unroll
        for (int ks = 0; ks < 4; ks++) {
            const int bb = ks & 1;
#pragma unroll
            for (int mf = 0; mf < 2; mf++) {
                const int s = ks * 2 + mf;            // 0..7
                const int ab = s & 1;

                // --- prefetch A frags for step s+1 (consumed 12 IMMAs later) ---
                if (s < 7) {
                    const uint32_t na = aoff[(s + 1) & 1] + (uint32_t)(((s + 1) >> 1) * 32);
                    ldsm4(a1f[ab ^ 1], st + OFF_A1 + na);
                    ldsm4(a2f[ab ^ 1], st + OFF_A2 + na);
                } else if (more) {
                    ldsm4(a1f[ab ^ 1], stn + OFF_A1 + aoff[0]);
                    ldsm4(a2f[ab ^ 1], stn + OFF_A2 + aoff[0]);
                }
                // --- prefetch B frags for next ks, spread over mf=0,1 ---
                {
                    const int np = mf;
                    if (ks < 3) {
                        const uint32_t nko = (uint32_t)((ks + 1) * 32);
                        ldB(b1[bb ^ 1], np, st + OFF_B1 + boff[np] + nko);
                        ldB(b2[bb ^ 1], np, st + OFF_B2 + boff[np] + nko);
                    } else if (more) {
                        ldB(b1[bb ^ 1], np, stn + OFF_B1 + boff[np]);
                        ldB(b2[bb ^ 1], np, stn + OFF_B2 + boff[np]);
                    }
                }

                // --- compute step s: 12 IMMAs on fully-resident fragments ---
#pragma unroll
                for (int nf = 0; nf < 4; nf++) imma(acch[mf][nf], a1f[ab], b1[bb][nf]);
#pragma unroll
                for (int nf = 0; nf < 4; nf++) imma(accm[mf][nf], a1f[ab], b2[bb][nf]);
#pragma unroll
                for (int nf = 0; nf < 4; nf++) imma(accm[mf][nf], a2f[ab], b1[bb][nf]);

                // stage prefetch for kc+2 after ks0 (LSU quiet zone)
                if (s == 1 && kc + 2 < NKC) {
                    int nb = buf + 2; if (nb >= 3) nb -= 3;
                    load_stage(nb, kc + 2);
                    cpa_commit();
                }
            }
        }
        buf = bufn;
    }
    __syncthreads();   // all warps done reading stages before epilogue reuses them

    // -------- epilogue: raw = 16384*hi + 128*mid staged in smem; GroupNorm per row --------
    float* ep = reinterpret_cast<float*>(smem + SM_STAGE);
    {
        const int r0 = wr * 32 + (lane >> 2);
        const int c0 = wc * 32 + (lane & 3) * 2;
#pragma unroll
        for (int mf = 0; mf < 2; mf++)
#pragma unroll
            for (int nf = 0; nf < 4; nf++) {
                const int r = r0 + mf * 16;
                const int c = c0 + nf * 8;
                float2 v0, v1;
                v0.x = fmaf(16384.f, (float)acch[mf][nf][0], 128.f * (float)accm[mf][nf][0]);
                v0.y = fmaf(16384.f, (float)acch[mf][nf][1], 128.f * (float)accm[mf][nf][1]);
                v1.x = fmaf(16384.f, (float)acch[mf][nf][2], 128.f * (float)accm[mf][nf][2]);
                v1.y = fmaf(16384.f, (float)acch[mf][nf][3], 128.f * (float)accm[mf][nf][3]);
                *reinterpret_cast<float2*>(ep + (size_t)r * EPS_LD + c) = v0;
                *reinterpret_cast<float2*>(ep + (size_t)(r + 8) * EPS_LD + c) = v1;
            }
    }
    __syncthreads();

    if (tid < BM) {
        const float sAr = g_sA[m0 + tid];
        const float4* row = reinterpret_cast<const float4*>(ep + (size_t)tid * EPS_LD);
        const float4* sb4 = reinterpret_cast<const float4*>(sbias);
        const float4* sc4 = reinterpret_cast<const float4*>(ssb);
        float sum = 0.f, sq = 0.f;
#pragma unroll
        for (int i = 0; i < 32; i++) {
            float4 v = row[i];
            float4 s = sc4[i];
            float4 b = sb4[i];
            float f0 = fmaf(sAr * s.x, v.x, b.x);
            float f1 = fmaf(sAr * s.y, v.y, b.y);
            float f2 = fmaf(sAr * s.z, v.z, b.z);
            float f3 = fmaf(sAr * s.w, v.w, b.w);
            sum += f0 + f1 + f2 + f3;
            sq += f0 * f0 + f1 * f1 + f2 * f2 + f3 * f3;
        }
        const float mean = sum * (1.0f / 128.0f);
        const float rstd = rsqrtf(sq * (1.0f / 128.0f) - mean * mean + EPS);
        float4* po = reinterpret_cast<float4*>(out + (size_t)(m0 + tid) * Ndim + n0);
#pragma unroll
        for (int i = 0; i < 32; i++) {
            float4 v = row[i];
            float4 s = sc4[i];
            float4 b = sb4[i];
            float4 o;
            o.x = fminf(fmaxf((fmaf(sAr * s.x, v.x, b.x) - mean) * rstd, -1.f), 1.f);
            o.y = fminf(fmaxf((fmaf(sAr * s.y, v.y, b.y) - mean) * rstd, -1.f), 1.f);
            o.z = fminf(fmaxf((fmaf(sAr * s.z, v.z, b.z) - mean) * rstd, -1.f), 1.f);
            o.w = fminf(fmaxf((fmaf(sAr * s.w, v.w, b.w) - mean) * rstd, -1.f), 1.f);
            po[i] = o;
        }
    }
}

extern "C" void kernel_launch(void* const* d_in, const int* in_sizes, int n_in,
                              void* d_out, int out_size) {
    const float* x = (const float*)d_in[0];
    const float* wgt = (const float*)d_in[1];
    const float* bias = (const float*)d_in[2];
    float* out = (float*)d_out;

    cudaFuncSetAttribute(gemm_gn_kernel, cudaFuncAttributeMaxDynamicSharedMemorySize,
                         (int)SMEM_TOTAL);

    quant_AB_kernel<<<Mdim + Ndim, 256>>>((const float4*)x, (const float4*)wgt);

    dim3 grid(Ndim / BN, Mdim / BM);   // (32, 64), x-fastest -> B set L2-resident
    gemm_gn_kernel<<<grid, NT, SMEM_TOTAL>>>(bias, out);
}